// round 3
// baseline (speedup 1.0000x reference)
#include <cuda_runtime.h>
#include <math.h>

#define B_TOTAL 65536
#define KDIM 512

// Ping-pong activation buffers (allocation-free scratch).
__device__ float g_bufA[(size_t)B_TOTAL * KDIM];
__device__ float g_bufB[(size_t)B_TOTAL * KDIM];

__device__ __forceinline__ float act_clip(float h, int f, float mx) {
    float o;
    if (f == 0) {
        o = fmaxf(h, 0.0f);                       // ReLU
    } else if (f == 1) {
        o = 1.0f / (1.0f + __expf(-h));           // Sigmoid
    } else if (f == 2) {
        o = tanhf(h);                             // Tanh
    } else if (f == 3) {
        o = (h > 0.0f) ? h : 0.1f * h;            // LeakyReLU(0.1)
    } else {
        const float sc = 1.0507009873554805f;     // SELU
        const float al = 1.6732632423543772f;
        o = (h > 0.0f) ? sc * h : sc * al * (__expf(h) - 1.0f);
    }
    return fminf(o, mx);
}

// C[M, N] = act_clip(A[M, K] @ W[N, K]^T + bias)   (K = 512 fixed)
// Block tile 128x128, BK=8, 256 threads, 8x8 per-thread microtile,
// double-buffered shared memory.
__global__ void __launch_bounds__(256)
fused_layer(const float* __restrict__ A,
            const float* __restrict__ W,
            const float* __restrict__ bias,
            const int*   __restrict__ fid,
            const float* __restrict__ mx,
            float* __restrict__ C,
            int N)
{
    constexpr int BM = 128, BK = 8, K = KDIM;
    __shared__ float As[2][BK][BM];
    __shared__ float Bs[2][BK][BM];

    const int bm  = blockIdx.x * BM;
    const int bn  = blockIdx.y * BM;
    const int tid = threadIdx.x;
    const int tx  = tid & 15;       // n-dim thread coord (0..15)
    const int ty  = tid >> 4;       // m-dim thread coord (0..15)

    // global->smem staging: each thread loads one float4 of A tile and W tile
    const int lrow = tid >> 1;           // 0..127
    const int lk   = (tid & 1) * 4;      // 0 or 4

    const float* Ap = A + (size_t)(bm + lrow) * K + lk;
    const float* Wp = W + (size_t)(bn + lrow) * K + lk;

    float acc[8][8];
    #pragma unroll
    for (int i = 0; i < 8; ++i)
        #pragma unroll
        for (int j = 0; j < 8; ++j) acc[i][j] = 0.0f;

    // prologue: stage k-tile 0
    float4 a4 = *(const float4*)Ap;
    float4 b4 = *(const float4*)Wp;
    As[0][lk+0][lrow] = a4.x; As[0][lk+1][lrow] = a4.y;
    As[0][lk+2][lrow] = a4.z; As[0][lk+3][lrow] = a4.w;
    Bs[0][lk+0][lrow] = b4.x; Bs[0][lk+1][lrow] = b4.y;
    Bs[0][lk+2][lrow] = b4.z; Bs[0][lk+3][lrow] = b4.w;
    __syncthreads();

    int buf = 0;
    constexpr int NT = K / BK;  // 64 k-tiles
    for (int kt = 0; kt < NT; ++kt) {
        if (kt + 1 < NT) {
            a4 = *(const float4*)(Ap + (kt + 1) * BK);
            b4 = *(const float4*)(Wp + (kt + 1) * BK);
        }
        #pragma unroll
        for (int k = 0; k < BK; ++k) {
            float4 ar0 = *(const float4*)&As[buf][k][ty * 8];
            float4 ar1 = *(const float4*)&As[buf][k][ty * 8 + 4];
            float4 br0 = *(const float4*)&Bs[buf][k][tx * 8];
            float4 br1 = *(const float4*)&Bs[buf][k][tx * 8 + 4];
            float ar[8] = {ar0.x, ar0.y, ar0.z, ar0.w, ar1.x, ar1.y, ar1.z, ar1.w};
            float br[8] = {br0.x, br0.y, br0.z, br0.w, br1.x, br1.y, br1.z, br1.w};
            #pragma unroll
            for (int i = 0; i < 8; ++i)
                #pragma unroll
                for (int j = 0; j < 8; ++j)
                    acc[i][j] = fmaf(ar[i], br[j], acc[i][j]);
        }
        if (kt + 1 < NT) {
            const int nb = buf ^ 1;
            As[nb][lk+0][lrow] = a4.x; As[nb][lk+1][lrow] = a4.y;
            As[nb][lk+2][lrow] = a4.z; As[nb][lk+3][lrow] = a4.w;
            Bs[nb][lk+0][lrow] = b4.x; Bs[nb][lk+1][lrow] = b4.y;
            Bs[nb][lk+2][lrow] = b4.z; Bs[nb][lk+3][lrow] = b4.w;
            __syncthreads();
            buf = nb;
        }
    }

    // epilogue: bias + per-column activation + clip, vectorized stores
    const int col0 = bn + tx * 8;
    float bv[8], mv[8];
    int   fv[8];
    #pragma unroll
    for (int j = 0; j < 8; ++j) {
        bv[j] = __ldg(bias + col0 + j);
        fv[j] = __ldg(fid  + col0 + j);
        mv[j] = __ldg(mx   + col0 + j);
    }
    #pragma unroll
    for (int i = 0; i < 8; ++i) {
        const int row = bm + ty * 8 + i;
        float v[8];
        #pragma unroll
        for (int j = 0; j < 8; ++j)
            v[j] = act_clip(acc[i][j] + bv[j], fv[j], mv[j]);
        *(float4*)(C + (size_t)row * N + col0)     = make_float4(v[0], v[1], v[2], v[3]);
        *(float4*)(C + (size_t)row * N + col0 + 4) = make_float4(v[4], v[5], v[6], v[7]);
    }
}

extern "C" void kernel_launch(void* const* d_in, const int* in_sizes, int n_in,
                              void* d_out, int out_size) {
    const float* x      = (const float*)d_in[0];   // [65536, 512]
    const float* W_in   = (const float*)d_in[1];   // [512, 512]
    const float* b_in   = (const float*)d_in[2];   // [512]
    const float* W_h    = (const float*)d_in[3];   // [4, 512, 512]
    const float* b_h    = (const float*)d_in[4];   // [4, 512]
    const float* W_out  = (const float*)d_in[5];   // [128, 512]
    const float* b_out  = (const float*)d_in[6];   // [128]
    const float* m_in   = (const float*)d_in[7];   // [512]
    const float* m_h    = (const float*)d_in[8];   // [4, 512]
    const float* m_out  = (const float*)d_in[9];   // [128]
    const int*   fid_in = (const int*)d_in[10];    // [512]
    const int*   fid_h  = (const int*)d_in[11];    // [4, 512]
    const int*   fid_out= (const int*)d_in[12];    // [128]
    float* out = (float*)d_out;                    // [65536, 128]

    float* bufA;
    float* bufB;
    cudaGetSymbolAddress((void**)&bufA, g_bufA);
    cudaGetSymbolAddress((void**)&bufB, g_bufB);

    dim3 blk(256);
    dim3 g512(B_TOTAL / 128, 512 / 128);
    dim3 g128(B_TOTAL / 128, 128 / 128);

    // input layer
    fused_layer<<<g512, blk>>>(x, W_in, b_in, fid_in, m_in, bufA, 512);

    // 4 hidden layers, ping-pong
    const float* cur = bufA;
    float* nxt = bufB;
    for (int i = 0; i < 4; ++i) {
        fused_layer<<<g512, blk>>>(cur,
                                   W_h + (size_t)i * 512 * 512,
                                   b_h + i * 512,
                                   fid_h + i * 512,
                                   m_h + i * 512,
                                   nxt, 512);
        float* t = nxt;
        nxt = (float*)cur;
        cur = t;
    }

    // output layer
    fused_layer<<<g128, blk>>>(cur, W_out, b_out, fid_out, m_out, out, 128);
}

// round 4
// speedup vs baseline: 1.0001x; 1.0001x over previous
#include <cuda_runtime.h>
#include <math.h>

#define B_TOTAL 65536
#define KDIM 512

// Ping-pong activation buffers (allocation-free scratch).
__device__ float g_bufA[(size_t)B_TOTAL * KDIM];
__device__ float g_bufB[(size_t)B_TOTAL * KDIM];

__device__ __forceinline__ float act_clip(float h, int f, float mx) {
    float o;
    if (f == 0) {
        o = fmaxf(h, 0.0f);                       // ReLU
    } else if (f == 1) {
        o = 1.0f / (1.0f + __expf(-h));           // Sigmoid
    } else if (f == 2) {
        o = tanhf(h);                             // Tanh
    } else if (f == 3) {
        o = (h > 0.0f) ? h : 0.1f * h;            // LeakyReLU(0.1)
    } else {
        const float sc = 1.0507009873554805f;     // SELU
        const float al = 1.6732632423543772f;
        o = (h > 0.0f) ? sc * h : sc * al * (__expf(h) - 1.0f);
    }
    return fminf(o, mx);
}

// C[M, N] = act_clip(A[M, K] @ W[N, K]^T + bias)   (K = 512 fixed)
// Block tile 128x128, BK=8, 256 threads, 8x8 per-thread microtile,
// double-buffered shared memory.
__global__ void __launch_bounds__(256)
fused_layer(const float* __restrict__ A,
            const float* __restrict__ W,
            const float* __restrict__ bias,
            const int*   __restrict__ fid,
            const float* __restrict__ mx,
            float* __restrict__ C,
            int N)
{
    constexpr int BM = 128, BK = 8, K = KDIM;
    __shared__ float As[2][BK][BM];
    __shared__ float Bs[2][BK][BM];

    const int bm  = blockIdx.x * BM;
    const int bn  = blockIdx.y * BM;
    const int tid = threadIdx.x;
    const int tx  = tid & 15;       // n-dim thread coord (0..15)
    const int ty  = tid >> 4;       // m-dim thread coord (0..15)

    // global->smem staging: each thread loads one float4 of A tile and W tile
    const int lrow = tid >> 1;           // 0..127
    const int lk   = (tid & 1) * 4;      // 0 or 4

    const float* Ap = A + (size_t)(bm + lrow) * K + lk;
    const float* Wp = W + (size_t)(bn + lrow) * K + lk;

    float acc[8][8];
    #pragma unroll
    for (int i = 0; i < 8; ++i)
        #pragma unroll
        for (int j = 0; j < 8; ++j) acc[i][j] = 0.0f;

    // prologue: stage k-tile 0
    float4 a4 = *(const float4*)Ap;
    float4 b4 = *(const float4*)Wp;
    As[0][lk+0][lrow] = a4.x; As[0][lk+1][lrow] = a4.y;
    As[0][lk+2][lrow] = a4.z; As[0][lk+3][lrow] = a4.w;
    Bs[0][lk+0][lrow] = b4.x; Bs[0][lk+1][lrow] = b4.y;
    Bs[0][lk+2][lrow] = b4.z; Bs[0][lk+3][lrow] = b4.w;
    __syncthreads();

    int buf = 0;
    constexpr int NT = K / BK;  // 64 k-tiles
    for (int kt = 0; kt < NT; ++kt) {
        if (kt + 1 < NT) {
            a4 = *(const float4*)(Ap + (kt + 1) * BK);
            b4 = *(const float4*)(Wp + (kt + 1) * BK);
        }
        #pragma unroll
        for (int k = 0; k < BK; ++k) {
            float4 ar0 = *(const float4*)&As[buf][k][ty * 8];
            float4 ar1 = *(const float4*)&As[buf][k][ty * 8 + 4];
            float4 br0 = *(const float4*)&Bs[buf][k][tx * 8];
            float4 br1 = *(const float4*)&Bs[buf][k][tx * 8 + 4];
            float ar[8] = {ar0.x, ar0.y, ar0.z, ar0.w, ar1.x, ar1.y, ar1.z, ar1.w};
            float br[8] = {br0.x, br0.y, br0.z, br0.w, br1.x, br1.y, br1.z, br1.w};
            #pragma unroll
            for (int i = 0; i < 8; ++i)
                #pragma unroll
                for (int j = 0; j < 8; ++j)
                    acc[i][j] = fmaf(ar[i], br[j], acc[i][j]);
        }
        if (kt + 1 < NT) {
            const int nb = buf ^ 1;
            As[nb][lk+0][lrow] = a4.x; As[nb][lk+1][lrow] = a4.y;
            As[nb][lk+2][lrow] = a4.z; As[nb][lk+3][lrow] = a4.w;
            Bs[nb][lk+0][lrow] = b4.x; Bs[nb][lk+1][lrow] = b4.y;
            Bs[nb][lk+2][lrow] = b4.z; Bs[nb][lk+3][lrow] = b4.w;
            __syncthreads();
            buf = nb;
        }
    }

    // epilogue: bias + per-column activation + clip, vectorized stores
    const int col0 = bn + tx * 8;
    float bv[8], mv[8];
    int   fv[8];
    #pragma unroll
    for (int j = 0; j < 8; ++j) {
        bv[j] = __ldg(bias + col0 + j);
        fv[j] = __ldg(fid  + col0 + j);
        mv[j] = __ldg(mx   + col0 + j);
    }
    #pragma unroll
    for (int i = 0; i < 8; ++i) {
        const int row = bm + ty * 8 + i;
        float v[8];
        #pragma unroll
        for (int j = 0; j < 8; ++j)
            v[j] = act_clip(acc[i][j] + bv[j], fv[j], mv[j]);
        *(float4*)(C + (size_t)row * N + col0)     = make_float4(v[0], v[1], v[2], v[3]);
        *(float4*)(C + (size_t)row * N + col0 + 4) = make_float4(v[4], v[5], v[6], v[7]);
    }
}

extern "C" void kernel_launch(void* const* d_in, const int* in_sizes, int n_in,
                              void* d_out, int out_size) {
    const float* x      = (const float*)d_in[0];   // [65536, 512]
    const float* W_in   = (const float*)d_in[1];   // [512, 512]
    const float* b_in   = (const float*)d_in[2];   // [512]
    const float* W_h    = (const float*)d_in[3];   // [4, 512, 512]
    const float* b_h    = (const float*)d_in[4];   // [4, 512]
    const float* W_out  = (const float*)d_in[5];   // [128, 512]
    const float* b_out  = (const float*)d_in[6];   // [128]
    const float* m_in   = (const float*)d_in[7];   // [512]
    const float* m_h    = (const float*)d_in[8];   // [4, 512]
    const float* m_out  = (const float*)d_in[9];   // [128]
    const int*   fid_in = (const int*)d_in[10];    // [512]
    const int*   fid_h  = (const int*)d_in[11];    // [4, 512]
    const int*   fid_out= (const int*)d_in[12];    // [128]
    float* out = (float*)d_out;                    // [65536, 128]

    float* bufA;
    float* bufB;
    cudaGetSymbolAddress((void**)&bufA, g_bufA);
    cudaGetSymbolAddress((void**)&bufB, g_bufB);

    dim3 blk(256);
    dim3 g512(B_TOTAL / 128, 512 / 128);
    dim3 g128(B_TOTAL / 128, 128 / 128);

    // input layer
    fused_layer<<<g512, blk>>>(x, W_in, b_in, fid_in, m_in, bufA, 512);

    // 4 hidden layers, ping-pong
    const float* cur = bufA;
    float* nxt = bufB;
    for (int i = 0; i < 4; ++i) {
        fused_layer<<<g512, blk>>>(cur,
                                   W_h + (size_t)i * 512 * 512,
                                   b_h + i * 512,
                                   fid_h + i * 512,
                                   m_h + i * 512,
                                   nxt, 512);
        float* t = nxt;
        nxt = (float*)cur;
        cur = t;
    }

    // output layer
    fused_layer<<<g128, blk>>>(cur, W_out, b_out, fid_out, m_out, out, 128);
}

// round 7
// speedup vs baseline: 1.0829x; 1.0828x over previous
#include <cuda_runtime.h>
#include <cstdint>
#include <math.h>

#define B_TOTAL 65536
#define KDIM 512

// Ping-pong activation buffers (allocation-free scratch).
__device__ float g_bufA[(size_t)B_TOTAL * KDIM];
__device__ float g_bufB[(size_t)B_TOTAL * KDIM];

__device__ __forceinline__ float act_clip(float h, int f, float mx) {
    float o;
    if (f == 0) {
        o = fmaxf(h, 0.0f);                       // ReLU
    } else if (f == 1) {
        o = 1.0f / (1.0f + __expf(-h));           // Sigmoid
    } else if (f == 2) {
        o = tanhf(h);                             // Tanh
    } else if (f == 3) {
        o = (h > 0.0f) ? h : 0.1f * h;            // LeakyReLU(0.1)
    } else {
        const float sc = 1.0507009873554805f;     // SELU
        const float al = 1.6732632423543772f;
        o = (h > 0.0f) ? sc * h : sc * al * (__expf(h) - 1.0f);
    }
    return fminf(o, mx);
}

__device__ __forceinline__ float f2tf32f(float x) {
    uint32_t r;
    asm("cvt.rna.tf32.f32 %0, %1;" : "=r"(r) : "f"(x));
    return __uint_as_float(r);
}

__device__ __forceinline__ void mma_tf32(float* d,
                                         float a0, float a1, float a2, float a3,
                                         float b0, float b1) {
    asm volatile(
        "mma.sync.aligned.m16n8k8.row.col.f32.tf32.tf32.f32 "
        "{%0,%1,%2,%3}, {%4,%5,%6,%7}, {%8,%9}, {%0,%1,%2,%3};"
        : "+f"(d[0]), "+f"(d[1]), "+f"(d[2]), "+f"(d[3])
        : "r"(__float_as_uint(a0)), "r"(__float_as_uint(a1)),
          "r"(__float_as_uint(a2)), "r"(__float_as_uint(a3)),
          "r"(__float_as_uint(b0)), "r"(__float_as_uint(b1)));
}

// Fragment slot permutation: element (x = row&7, ci = k&3) lives at 16B granule
// sigma = (r12<<3) | (r0<<2) | (ci ^ r12).  Conflict-free for consumer LDS.128
// and for producer STS.32 with the staging thread maps below.
__device__ __forceinline__ int frag_sigma(int x, int ci) {
    const int r0 = x & 1;
    const int r12 = (x >> 1) & 3;
    return (r12 << 3) | (r0 << 2) | (ci ^ r12);
}

// Block stride padded: 128 floats + 4 pad = 132 (keeps 16B alignment, rotates banks)
#define BLK 132
#define A_SSTRIDE (8 * BLK)      // per k-step s: 8 m-tiles
#define B_GSTRIDE (16 * BLK)     // per k-group g: 16 n-tiles
#define A_TILE_FLOATS (4 * A_SSTRIDE)
#define B_TILE_FLOATS (2 * B_GSTRIDE)
// smem: sA_hi, sA_lo, sB_hi, sB_lo
#define SMEM_FLOATS (2 * A_TILE_FLOATS + 2 * B_TILE_FLOATS)
#define SMEM_BYTES (SMEM_FLOATS * 4)

// C[M, N] = act_clip(A[M,512] @ W[N,512]^T + bias), 3xTF32 mma.sync path.
// CTA: 128x128 tile, BK=32, 256 threads = 8 warps of 32x64.
__global__ void __launch_bounds__(256)
fused_layer_mma3(const float* __restrict__ A,
                 const float* __restrict__ W,
                 const float* __restrict__ bias,
                 const int*   __restrict__ fid,
                 const float* __restrict__ mx,
                 float* __restrict__ C,
                 int N)
{
    extern __shared__ __align__(16) float smem[];
    float* sAh = smem;
    float* sAl = sAh + A_TILE_FLOATS;
    float* sBh = sAl + A_TILE_FLOATS;
    float* sBl = sBh + B_TILE_FLOATS;

    const int tid = threadIdx.x;
    const int w   = tid >> 5;
    const int l   = tid & 31;

    const int bn = blockIdx.x * 128;
    const int bm = blockIdx.y * 128;

    // ---- staging maps ----
    // A: thread t -> row ar = t>>1, k-half ahk = t&1.
    const int ar  = tid >> 1;
    const int ahk = tid & 1;
    const int arr = ar & 15;
    const int atm = ar >> 4;
    const int areg = (arr >> 3) + 2 * ahk;
    int aslot[4];
    #pragma unroll
    for (int ci = 0; ci < 4; ++ci)
        aslot[ci] = atm * BLK + 4 * frag_sigma(arr & 7, ci) + areg;

    // B: thread t -> n rows {t>>2, t>>2 + 64}, j = t&3.
    const int bj = tid & 3;
    const int bn0 = tid >> 2;      // 0..63
    int bslot[2][4];
    #pragma unroll
    for (int half = 0; half < 2; ++half) {
        const int n = bn0 + 64 * half;
        #pragma unroll
        for (int ci = 0; ci < 4; ++ci)
            bslot[half][ci] = (n >> 3) * BLK + 4 * frag_sigma(n & 7, ci) + bj;
    }

    const float* Abase = A + (size_t)(bm + ar) * KDIM + ahk * 4;
    const float* Wb0   = W + (size_t)(bn + bn0) * KDIM + bj * 4;
    const float* Wb1   = Wb0 + (size_t)64 * KDIM;

    // ---- consumer map ----
    const int wm = w & 3;          // m block: rows wm*32
    const int wn = w >> 2;         // n block: cols wn*64
    const int sig4 = 4 * frag_sigma(l >> 2, l & 3);

    float acc[2][8][4];
    #pragma unroll
    for (int i = 0; i < 2; ++i)
        #pragma unroll
        for (int u = 0; u < 8; ++u)
            #pragma unroll
            for (int r = 0; r < 4; ++r) acc[i][u][r] = 0.0f;

    // prologue prefetch (chunk 0)
    float4 pa[4], pb[4];
    #pragma unroll
    for (int rep = 0; rep < 4; ++rep) {
        pa[rep] = *(const float4*)(Abase + rep * 8);
        pb[rep] = *(const float4*)(((rep >> 1) ? Wb1 : Wb0) + (rep & 1) * 16);
    }

    constexpr int NCHUNK = KDIM / 32;   // 16
    for (int kc = 0; kc < NCHUNK; ++kc) {
        // stage hi/lo splits
        #pragma unroll
        for (int rep = 0; rep < 4; ++rep) {
            const float va[4] = {pa[rep].x, pa[rep].y, pa[rep].z, pa[rep].w};
            float* ah = sAh + rep * A_SSTRIDE;
            float* al = sAl + rep * A_SSTRIDE;
            #pragma unroll
            for (int ci = 0; ci < 4; ++ci) {
                const float hi = f2tf32f(va[ci]);
                ah[aslot[ci]] = hi;
                al[aslot[ci]] = f2tf32f(va[ci] - hi);
            }
            const float vb[4] = {pb[rep].x, pb[rep].y, pb[rep].z, pb[rep].w};
            float* bh = sBh + (rep & 1) * B_GSTRIDE;
            float* bl = sBl + (rep & 1) * B_GSTRIDE;
            const int* bsl = bslot[rep >> 1];
            #pragma unroll
            for (int ci = 0; ci < 4; ++ci) {
                const float hi = f2tf32f(vb[ci]);
                bh[bsl[ci]] = hi;
                bl[bsl[ci]] = f2tf32f(vb[ci] - hi);
            }
        }
        __syncthreads();

        if (kc + 1 < NCHUNK) {   // prefetch next chunk; overlaps with mma below
            const int ko = (kc + 1) * 32;
            #pragma unroll
            for (int rep = 0; rep < 4; ++rep) {
                pa[rep] = *(const float4*)(Abase + ko + rep * 8);
                pb[rep] = *(const float4*)(((rep >> 1) ? Wb1 : Wb0) + ko + (rep & 1) * 16);
            }
        }

        #pragma unroll
        for (int g = 0; g < 2; ++g) {
            #pragma unroll
            for (int un = 0; un < 2; ++un) {
                float4 bqh[4], bql[4];
                #pragma unroll
                for (int uq = 0; uq < 4; ++uq) {
                    const int u = wn * 8 + un * 4 + uq;
                    bqh[uq] = *(const float4*)&sBh[(g * 16 + u) * BLK + sig4];
                    bql[uq] = *(const float4*)&sBl[(g * 16 + u) * BLK + sig4];
                }
                #pragma unroll
                for (int p = 0; p < 2; ++p) {
                    const int s = 2 * g + p;
                    const int abase0 = (s * 8 + 2 * wm + 0) * BLK + sig4;
                    const int abase1 = (s * 8 + 2 * wm + 1) * BLK + sig4;
                    const float4 ah0 = *(const float4*)&sAh[abase0];
                    const float4 ah1 = *(const float4*)&sAh[abase1];
                    const float4 al0 = *(const float4*)&sAl[abase0];
                    const float4 al1 = *(const float4*)&sAl[abase1];
                    #pragma unroll
                    for (int uq = 0; uq < 4; ++uq) {
                        const float b0h = p ? bqh[uq].z : bqh[uq].x;
                        const float b1h = p ? bqh[uq].w : bqh[uq].y;
                        const float b0l = p ? bql[uq].z : bql[uq].x;
                        const float b1l = p ? bql[uq].w : bql[uq].y;
                        float* a0 = acc[0][un * 4 + uq];
                        float* a1 = acc[1][un * 4 + uq];
                        // hi*hi + hi*lo + lo*hi  (lo*lo dropped: ~2^-22)
                        mma_tf32(a0, ah0.x, ah0.y, ah0.z, ah0.w, b0h, b1h);
                        mma_tf32(a0, ah0.x, ah0.y, ah0.z, ah0.w, b0l, b1l);
                        mma_tf32(a0, al0.x, al0.y, al0.z, al0.w, b0h, b1h);
                        mma_tf32(a1, ah1.x, ah1.y, ah1.z, ah1.w, b0h, b1h);
                        mma_tf32(a1, ah1.x, ah1.y, ah1.z, ah1.w, b0l, b1l);
                        mma_tf32(a1, al1.x, al1.y, al1.z, al1.w, b0h, b1h);
                    }
                }
            }
        }
        __syncthreads();
    }

    // ---- epilogue: bias + per-column activation + clip ----
    #pragma unroll
    for (int uu = 0; uu < 8; ++uu) {
        const int col = bn + wn * 64 + uu * 8 + (l & 3) * 2;
        const float bv0 = __ldg(bias + col);
        const float bv1 = __ldg(bias + col + 1);
        const int   f0  = __ldg(fid + col);
        const int   f1  = __ldg(fid + col + 1);
        const float m0  = __ldg(mx + col);
        const float m1  = __ldg(mx + col + 1);
        #pragma unroll
        for (int i = 0; i < 2; ++i) {
            const int row0 = bm + wm * 32 + i * 16 + (l >> 2);
            const float* a4 = acc[i][uu];
            float2 v0, v1;
            v0.x = act_clip(a4[0] + bv0, f0, m0);
            v0.y = act_clip(a4[1] + bv1, f1, m1);
            v1.x = act_clip(a4[2] + bv0, f0, m0);
            v1.y = act_clip(a4[3] + bv1, f1, m1);
            *(float2*)(C + (size_t)row0 * N + col)       = v0;
            *(float2*)(C + (size_t)(row0 + 8) * N + col) = v1;
        }
    }
}

extern "C" void kernel_launch(void* const* d_in, const int* in_sizes, int n_in,
                              void* d_out, int out_size) {
    const float* x      = (const float*)d_in[0];   // [65536, 512]
    const float* W_in   = (const float*)d_in[1];   // [512, 512]
    const float* b_in   = (const float*)d_in[2];   // [512]
    const float* W_h    = (const float*)d_in[3];   // [4, 512, 512]
    const float* b_h    = (const float*)d_in[4];   // [4, 512]
    const float* W_out  = (const float*)d_in[5];   // [128, 512]
    const float* b_out  = (const float*)d_in[6];   // [128]
    const float* m_in   = (const float*)d_in[7];   // [512]
    const float* m_h    = (const float*)d_in[8];   // [4, 512]
    const float* m_out  = (const float*)d_in[9];   // [128]
    const int*   fid_in = (const int*)d_in[10];    // [512]
    const int*   fid_h  = (const int*)d_in[11];    // [4, 512]
    const int*   fid_out= (const int*)d_in[12];    // [128]
    float* out = (float*)d_out;                    // [65536, 128]

    float* bufA;
    float* bufB;
    cudaGetSymbolAddress((void**)&bufA, g_bufA);
    cudaGetSymbolAddress((void**)&bufB, g_bufB);

    // Idempotent (no static guard): ~66KB dynamic smem for hi/lo tiles.
    cudaFuncSetAttribute(fused_layer_mma3,
                         cudaFuncAttributeMaxDynamicSharedMemorySize, SMEM_BYTES);

    dim3 blk(256);
    dim3 g512(512 / 128, B_TOTAL / 128);   // N-tiles fastest -> A-tile L2 reuse
    dim3 g128(128 / 128, B_TOTAL / 128);

    // input layer
    fused_layer_mma3<<<g512, blk, SMEM_BYTES>>>(x, W_in, b_in, fid_in, m_in, bufA, 512);

    // 4 hidden layers, ping-pong
    const float* cur = bufA;
    float* nxt = bufB;
    for (int i = 0; i < 4; ++i) {
        fused_layer_mma3<<<g512, blk, SMEM_BYTES>>>(cur,
                                                    W_h + (size_t)i * 512 * 512,
                                                    b_h + i * 512,
                                                    fid_h + i * 512,
                                                    m_h + i * 512,
                                                    nxt, 512);
        float* t = nxt;
        nxt = (float*)cur;
        cur = t;
    }

    // output layer
    fused_layer_mma3<<<g128, blk, SMEM_BYTES>>>(cur, W_out, b_out, fid_out, m_out, out, 128);
}